// round 15
// baseline (speedup 1.0000x reference)
#include <cuda_runtime.h>
#include <cuda_bf16.h>
#include <cstdint>

// ---------------------------------------------------------------------------
// Problem constants
// ---------------------------------------------------------------------------
constexpr int NB   = 16;
constexpr int N1v  = 4096;
constexpr int N2v  = 1024;
constexpr int C1v  = 128;
constexpr int C2v  = 256;
constexpr int CINv = 384;
constexpr int M0v  = 256;
constexpr int M1v  = 128;
constexpr int NTOTv = NB * N1v;   // 65536
#define BN_EPS 1e-5f

// ---------------------------------------------------------------------------
// Scratch (device globals)
// ---------------------------------------------------------------------------
__device__ uint16_t g_Xh[(size_t)CINv * NTOTv];
__device__ uint16_t g_Xl[(size_t)CINv * NTOTv];
__device__ uint16_t g_w0h[M0v * CINv], g_w0l[M0v * CINv];
__device__ uint16_t g_w1h[M1v * M0v],  g_w1l[M1v * M0v];
__device__ float g_y0[(size_t)M0v * NTOTv];
__device__ float g_y1[(size_t)M1v * NTOTv];
__device__ int   g_idx3[NTOTv * 3];
__device__ float g_w3[NTOTv * 3];
__device__ float g_s0[M0v], g_q0[M0v];
__device__ float g_s1[M1v], g_q1[M1v];
__device__ int   g_ctr1, g_ctr2;

// ---------------------------------------------------------------------------
// Helpers
// ---------------------------------------------------------------------------
__device__ __forceinline__ uint32_t smem_u32(const void* p) {
    uint32_t a;
    asm("{ .reg .u64 t; cvta.to.shared.u64 t, %1; cvt.u32.u64 %0, t; }"
        : "=r"(a) : "l"(p));
    return a;
}

__device__ __forceinline__ void split2(float x0, float x1, uint32_t& h, uint32_t& l) {
    uint32_t hh;
    asm("cvt.rn.bf16x2.f32 %0, %1, %2;" : "=r"(hh) : "f"(x1), "f"(x0));
    const float h0 = __uint_as_float(hh << 16);
    const float h1 = __uint_as_float(hh & 0xFFFF0000u);
    const float l0 = x0 - h0;
    const float l1 = x1 - h1;
    uint32_t ll;
    asm("cvt.rn.bf16x2.f32 %0, %1, %2;" : "=r"(ll) : "f"(l1), "f"(l0));
    h = hh; l = ll;
}

__device__ __forceinline__ void split1(float x, uint16_t& h, uint16_t& l) {
    __nv_bfloat16 hb = __float2bfloat16(x);
    const float hf = __bfloat162float(hb);
    __nv_bfloat16 lb = __float2bfloat16(x - hf);
    h = *reinterpret_cast<uint16_t*>(&hb);
    l = *reinterpret_cast<uint16_t*>(&lb);
}

__device__ __forceinline__ void mma16(float* d, const uint32_t* a,
                                      uint32_t b0, uint32_t b1) {
    asm volatile(
        "mma.sync.aligned.m16n8k16.row.col.f32.bf16.bf16.f32 "
        "{%0,%1,%2,%3}, {%4,%5,%6,%7}, {%8,%9}, {%0,%1,%2,%3};"
        : "+f"(d[0]), "+f"(d[1]), "+f"(d[2]), "+f"(d[3])
        : "r"(a[0]), "r"(a[1]), "r"(a[2]), "r"(a[3]), "r"(b0), "r"(b1));
}

__device__ __forceinline__ void ldsm4(uint32_t* r, uint32_t a) {
    asm volatile("ldmatrix.sync.aligned.m8n8.x4.shared.b16 {%0,%1,%2,%3}, [%4];"
        : "=r"(r[0]), "=r"(r[1]), "=r"(r[2]), "=r"(r[3]) : "r"(a));
}
__device__ __forceinline__ void ldsm4t(uint32_t* r, uint32_t a) {
    asm volatile("ldmatrix.sync.aligned.m8n8.x4.trans.shared.b16 {%0,%1,%2,%3}, [%4];"
        : "=r"(r[0]), "=r"(r[1]), "=r"(r[2]), "=r"(r[3]) : "r"(a));
}
__device__ __forceinline__ void cpasync16(uint32_t dst, const void* src) {
    asm volatile("cp.async.cg.shared.global [%0], [%1], 16;" :: "r"(dst), "l"(src));
}
__device__ __forceinline__ void cpcommit() {
    asm volatile("cp.async.commit_group;" ::: "memory");
}

// ---------------------------------------------------------------------------
// Shared GEMM SMEM geometry: A[128][40] u16, B [k][j] 32x[136]
// ---------------------------------------------------------------------------
constexpr int G_SA    = 40;
constexpr int G_SB    = 136;
constexpr int G_ALO   = 128 * G_SA;
constexpr int G_BHI   = 2 * 128 * G_SA;
constexpr int G_BLO   = G_BHI + 32 * G_SB;
constexpr int G_STG   = G_BHI + 2 * 32 * G_SB;   // 18944 u16
constexpr int G_STGB  = G_STG * 2;               // 37888 bytes

// ---------------------------------------------------------------------------
// prep_knn: blocks [0,256) = 3-NN (branchless top-3); rest = prep.
// ---------------------------------------------------------------------------
__global__ __launch_bounds__(256) void prep_knn(const float* __restrict__ w0,
                                                const float* __restrict__ w1,
                                                const float* __restrict__ feat1,
                                                const float* __restrict__ xyz1,
                                                const float* __restrict__ xyz2)
{
    __shared__ float4 s2[N2v];
    const int tid = threadIdx.x;

    if (blockIdx.x < 256) {
        const int b  = blockIdx.x >> 4;
        const int nb = blockIdx.x & 15;
        const float* x2 = xyz2 + (size_t)b * N2v * 3;
        for (int i = tid; i < N2v; i += 256)
            s2[i] = make_float4(x2[i * 3 + 0], x2[i * 3 + 1], x2[i * 3 + 2], 0.0f);
        __syncthreads();

        const int n = nb * 256 + tid;
        const float* p = xyz1 + ((size_t)b * N1v + n) * 3;
        const float px = p[0], py = p[1], pz = p[2];

        float d0 = 1e30f, d1 = 1e30f, d2 = 1e30f;
        int   i0 = 0,     i1 = 0,     i2 = 0;

        // Branchless top-3: predicated selects, zero warp divergence.
        #pragma unroll 4
        for (int i = 0; i < N2v; i++) {
            const float4 qv = s2[i];
            const float dx = px - qv.x, dy = py - qv.y, dz = pz - qv.z;
            float d = dx * dx;
            d = fmaf(dy, dy, d);
            d = fmaf(dz, dz, d);
            const bool c2 = d < d2;
            const bool c1 = d < d1;
            const bool c0 = d < d0;
            d2 = c1 ? d1 : (c2 ? d : d2);
            i2 = c1 ? i1 : (c2 ? i : i2);
            d1 = c0 ? d0 : (c1 ? d : d1);
            i1 = c0 ? i0 : (c1 ? i : i1);
            d0 = c0 ? d  : d0;
            i0 = c0 ? i  : i0;
        }

        const float w0_ = 1.0f / (d0 + 1e-8f);
        const float w1_ = 1.0f / (d1 + 1e-8f);
        const float w2_ = 1.0f / (d2 + 1e-8f);
        const float inv = 1.0f / (w0_ + w1_ + w2_);

        const int base = ((size_t)b * N1v + n) * 3;
        g_idx3[base + 0] = i0; g_idx3[base + 1] = i1; g_idx3[base + 2] = i2;
        g_w3[base + 0] = w0_ * inv;
        g_w3[base + 1] = w1_ * inv;
        g_w3[base + 2] = w2_ * inv;
    } else {
        const int pidx = blockIdx.x - 256;
        const int gidx = pidx * 256 + tid;

        if (pidx == 0) {
            if (tid < M0v) { g_s0[tid] = 0.0f; g_q0[tid] = 0.0f; }
            if (tid < M1v) { g_s1[tid] = 0.0f; g_q1[tid] = 0.0f; }
            if (tid == 0)  { g_ctr1 = 0; g_ctr2 = 0; }
        }
        if (gidx < M0v * CINv) {
            uint16_t h, l;
            split1(w0[gidx], h, l);
            g_w0h[gidx] = h;
            g_w0l[gidx] = l;
        }
        if (gidx < M1v * M0v) {
            uint16_t h, l;
            split1(w1[gidx], h, l);
            g_w1h[gidx] = h;
            g_w1l[gidx] = l;
        }

        const int e = gidx * 4;
        float4 v = *(const float4*)(feat1 + e);
        const int b = e >> 19, c = (e >> 12) & 127, n = e & 4095;
        const size_t dst = (size_t)c * NTOTv + b * N1v + n;
        uint32_t h0, l0, h1, l1;
        split2(v.x, v.y, h0, l0);
        split2(v.z, v.w, h1, l1);
        *(uint32_t*)(g_Xh + dst)     = h0;
        *(uint32_t*)(g_Xh + dst + 2) = h1;
        *(uint32_t*)(g_Xl + dst)     = l0;
        *(uint32_t*)(g_Xl + dst + 2) = l1;
    }
}

// ---------------------------------------------------------------------------
// Interpolation (single launch, 128 blocks)
// ---------------------------------------------------------------------------
constexpr int IT_STR  = 36;
constexpr int IT_SMEM = N2v * IT_STR * 4;

__global__ __launch_bounds__(256) void interp_tiled(const float* __restrict__ feat2)
{
    extern __shared__ float tile[];
    const int b  = blockIdx.x >> 3;
    const int cg = blockIdx.x & 7;
    const float* src = feat2 + ((size_t)b * C2v + cg * 32) * N2v;
    for (int x = threadIdx.x; x < 32 * N2v; x += 256) {
        const int c = x >> 10, i = x & 1023;
        tile[i * IT_STR + c] = src[x];
    }
    __syncthreads();

    for (int jb = threadIdx.x * 2; jb < N1v; jb += 512) {
        const int jg = b * N1v + jb;
        const int pa = jg * 3;
        const int ia0 = g_idx3[pa + 0], ia1 = g_idx3[pa + 1], ia2 = g_idx3[pa + 2];
        const int ib0 = g_idx3[pa + 3], ib1 = g_idx3[pa + 4], ib2 = g_idx3[pa + 5];
        const float wa0 = g_w3[pa + 0], wa1 = g_w3[pa + 1], wa2 = g_w3[pa + 2];
        const float wb0 = g_w3[pa + 3], wb1 = g_w3[pa + 4], wb2 = g_w3[pa + 5];
        const float* ta0 = tile + ia0 * IT_STR;
        const float* ta1 = tile + ia1 * IT_STR;
        const float* ta2 = tile + ia2 * IT_STR;
        const float* tb0 = tile + ib0 * IT_STR;
        const float* tb1 = tile + ib1 * IT_STR;
        const float* tb2 = tile + ib2 * IT_STR;

        #pragma unroll
        for (int c4 = 0; c4 < 8; c4++) {
            const float4 A0 = *(const float4*)(ta0 + c4 * 4);
            const float4 A1 = *(const float4*)(ta1 + c4 * 4);
            const float4 A2 = *(const float4*)(ta2 + c4 * 4);
            const float4 B0 = *(const float4*)(tb0 + c4 * 4);
            const float4 B1 = *(const float4*)(tb1 + c4 * 4);
            const float4 B2 = *(const float4*)(tb2 + c4 * 4);
            float va[4], vb[4];
            va[0] = fmaf(wa2, A2.x, fmaf(wa1, A1.x, wa0 * A0.x));
            va[1] = fmaf(wa2, A2.y, fmaf(wa1, A1.y, wa0 * A0.y));
            va[2] = fmaf(wa2, A2.z, fmaf(wa1, A1.z, wa0 * A0.z));
            va[3] = fmaf(wa2, A2.w, fmaf(wa1, A1.w, wa0 * A0.w));
            vb[0] = fmaf(wb2, B2.x, fmaf(wb1, B1.x, wb0 * B0.x));
            vb[1] = fmaf(wb2, B2.y, fmaf(wb1, B1.y, wb0 * B0.y));
            vb[2] = fmaf(wb2, B2.z, fmaf(wb1, B1.z, wb0 * B0.z));
            vb[3] = fmaf(wb2, B2.w, fmaf(wb1, B1.w, wb0 * B0.w));
            #pragma unroll
            for (int qx = 0; qx < 4; qx++) {
                uint32_t h, l;
                split2(va[qx], vb[qx], h, l);
                const size_t d = (size_t)(C1v + cg * 32 + c4 * 4 + qx) * NTOTv + jg;
                *(uint32_t*)(g_Xh + d) = h;
                *(uint32_t*)(g_Xl + d) = l;
            }
        }
    }
}

// ---------------------------------------------------------------------------
// GEMM1 (R12: persistent + cross-tile pipelining)
// ---------------------------------------------------------------------------
constexpr int G1_NC   = CINv / 32;               // 12
constexpr int G1_SMEM = 3 * G_STGB;              // 113664 bytes
constexpr int G1_NT   = (M0v / 128) * (NTOTv / 128);  // 1024

__global__ __launch_bounds__(256, 2) void gemm1(const float* __restrict__ bias)
{
    extern __shared__ uint16_t sm1[];
    __shared__ int sh_t[2];
    const uint32_t smb = smem_u32(sm1);
    const int tid  = threadIdx.x;
    const int lane = tid & 31;
    const int wid  = tid >> 5;
    const int wm   = wid >> 2;
    const int wn   = wid & 3;

    const int q  = lane >> 3;
    const int jj = lane & 7;
    const uint32_t aoff = ((wm * 64 + (q & 1) * 8 + jj) * G_SA + (q >> 1) * 8) * 2;
    const uint32_t boff = (G_BHI + ((q & 1) * 8 + jj) * G_SB
                           + wn * 32 + (q >> 1) * 8) * 2;

    auto issue = [&](int m0g, int j0, int c) {
        const int k0 = c * 32;
        const uint32_t sb = smb + (c % 3) * G_STGB;
        #pragma unroll
        for (int g = 0; g < 2; g++) {
            const int idx = 2 * tid + g;
            const int m  = idx >> 2, ch = idx & 3;
            const uint16_t* sa = g_w0h + (size_t)(m0g + m) * CINv + k0 + ch * 8;
            const uint16_t* sl = g_w0l + (size_t)(m0g + m) * CINv + k0 + ch * 8;
            const uint32_t da = sb + (m * G_SA + ch * 8) * 2;
            cpasync16(da, sa);
            cpasync16(da + G_ALO * 2, sl);
            const int k = idx >> 4, ch2 = idx & 15;
            const uint16_t* sbh = g_Xh + (size_t)(k0 + k) * NTOTv + j0 + ch2 * 8;
            const uint16_t* sbl = g_Xl + (size_t)(k0 + k) * NTOTv + j0 + ch2 * 8;
            const uint32_t db = sb + (G_BHI + k * G_SB + ch2 * 8) * 2;
            cpasync16(db, sbh);
            cpasync16(db + (G_BLO - G_BHI) * 2, sbl);
        }
        cpcommit();
    };

    if (tid == 0) sh_t[0] = atomicAdd(&g_ctr1, 1);
    __syncthreads();
    int t = sh_t[0];
    if (t >= G1_NT) return;
    int pr = 0;
    int m0g = (t & 1) * 128;
    int j0  = (t >> 1) * 128;
    issue(m0g, j0, 0);
    issue(m0g, j0, 1);

    int tn = 0;
    for (;;) {
        float acc[4][4][4] = {};

        auto compute = [&](int i) {
            const uint32_t sb = smb + (i % 3) * G_STGB;
            #pragma unroll
            for (int ks = 0; ks < 2; ks++) {
                uint32_t ah[4][4], al[4][4], bh[2][4], bl[2][4];
                #pragma unroll
                for (int mi = 0; mi < 4; mi++) {
                    const uint32_t a = sb + aoff + mi * (16 * G_SA * 2) + ks * 32;
                    ldsm4(ah[mi], a);
                    ldsm4(al[mi], a + G_ALO * 2);
                }
                #pragma unroll
                for (int nb = 0; nb < 2; nb++) {
                    const uint32_t a = sb + boff + ks * (16 * G_SB * 2) + nb * 32;
                    ldsm4t(bh[nb], a);
                    ldsm4t(bl[nb], a + (G_BLO - G_BHI) * 2);
                }
                #pragma unroll
                for (int ni = 0; ni < 4; ni++) {
                    const uint32_t b0h = bh[ni >> 1][(ni & 1) * 2];
                    const uint32_t b1h = bh[ni >> 1][(ni & 1) * 2 + 1];
                    const uint32_t b0l = bl[ni >> 1][(ni & 1) * 2];
                    const uint32_t b1l = bl[ni >> 1][(ni & 1) * 2 + 1];
                    #pragma unroll
                    for (int mi = 0; mi < 4; mi++) {
                        mma16(acc[mi][ni], ah[mi], b0h, b1h);
                        mma16(acc[mi][ni], ah[mi], b0l, b1l);
                        mma16(acc[mi][ni], al[mi], b0h, b1h);
                    }
                }
            }
        };

        #pragma unroll 1
        for (int i = 0; i < G1_NC; i++) {
            if (i == G1_NC - 3 && tid == 0)
                sh_t[pr ^ 1] = atomicAdd(&g_ctr1, 1);
            if (i == G1_NC - 1 && tn >= G1_NT)
                asm volatile("cp.async.wait_group 0;" ::: "memory");
            else
                asm volatile("cp.async.wait_group 1;" ::: "memory");
            __syncthreads();
            if (i == G1_NC - 2) tn = sh_t[pr ^ 1];
            if (i < G1_NC - 2) {
                issue(m0g, j0, i + 2);
            } else if (tn < G1_NT) {
                issue((tn & 1) * 128, (tn >> 1) * 128, i - (G1_NC - 2));
            }
            compute(i);
        }

        #pragma unroll
        for (int mi = 0; mi < 4; mi++) {
            const int mrow = m0g + wm * 64 + mi * 16 + (lane >> 2);
            #pragma unroll
            for (int half = 0; half < 2; half++) {
                const int m = mrow + half * 8;
                const float bv = bias[m];
                float* orow = g_y0 + (size_t)m * NTOTv + j0 + wn * 32 + 2 * (lane & 3);
                float s = 0.0f, qq = 0.0f;
                #pragma unroll
                for (int ni = 0; ni < 4; ni++) {
                    const float v0 = acc[mi][ni][half * 2 + 0] + bv;
                    const float v1 = acc[mi][ni][half * 2 + 1] + bv;
                    s += v0 + v1;
                    qq = fmaf(v0, v0, qq);
                    qq = fmaf(v1, v1, qq);
                    *(float2*)(orow + ni * 8) = make_float2(v0, v1);
                }
                s  += __shfl_xor_sync(0xffffffffu, s, 1);
                s  += __shfl_xor_sync(0xffffffffu, s, 2);
                qq += __shfl_xor_sync(0xffffffffu, qq, 1);
                qq += __shfl_xor_sync(0xffffffffu, qq, 2);
                if ((lane & 3) == 0) {
                    atomicAdd(g_s0 + m, s);
                    atomicAdd(g_q0 + m, qq);
                }
            }
        }

        if (tn >= G1_NT) break;
        t = tn;
        m0g = (t & 1) * 128;
        j0  = (t >> 1) * 128;
        pr ^= 1;
    }
}

// ---------------------------------------------------------------------------
// GEMM2 (R11 schedule): persistent, depth-1 pipeline, fp32 staging + convert
// ---------------------------------------------------------------------------
constexpr int G2_NC    = M0v / 32;             // 8
constexpr int G2_FP32  = 2 * G_STG;
constexpr int G2_FPU16 = 32 * 128 * 2;
constexpr int G2_SMEM  = 2 * G_STGB + 2 * 16384;  // 108544 bytes
constexpr int G2_NT    = NTOTv / 128;          // 512

__global__ __launch_bounds__(256, 2) void gemm2(const float* __restrict__ bias,
                                                const float* __restrict__ g0v,
                                                const float* __restrict__ be0v)
{
    extern __shared__ uint16_t sm2[];
    __shared__ float s_scale[M0v], s_shift[M0v];
    __shared__ int sh_t;
    const uint32_t smb = smem_u32(sm2);

    const int tid  = threadIdx.x;
    const int lane = tid & 31;
    const int wid  = tid >> 5;
    const int wm   = wid >> 2;
    const int wn   = wid & 3;

    {
        const int c = tid;
        const float mean = g_s0[c] * (1.0f / NTOTv);
        const float var  = g_q0[c] * (1.0f / NTOTv) - mean * mean;
        const float sc = g0v[c] * rsqrtf(var + BN_EPS);
        s_scale[c] = sc;
        s_shift[c] = be0v[c] - mean * sc;
    }

    const int q  = lane >> 3;
    const int jj = lane & 7;
    const uint32_t aoff = ((wm * 64 + (q & 1) * 8 + jj) * G_SA + (q >> 1) * 8) * 2;
    const uint32_t boff = (G_BHI + ((q & 1) * 8 + jj) * G_SB
                           + wn * 32 + (q >> 1) * 8) * 2;

    for (;;) {
        __syncthreads();
        if (tid == 0) sh_t = atomicAdd(&g_ctr2, 1);
        __syncthreads();
        const int t = sh_t;
        if (t >= G2_NT) break;
        const int j0 = t * 128;

        float acc[4][4][4] = {};

        auto issue = [&](int i) {
            const int k0 = i * 32;
            const int s  = i & 1;
            const uint32_t sb = smb + s * G_STGB;
            #pragma unroll
            for (int g = 0; g < 2; g++) {
                const int idx = 2 * tid + g;
                const int m  = idx >> 2, ch = idx & 3;
                const uint16_t* sa = g_w1h + (size_t)m * M0v + k0 + ch * 8;
                const uint16_t* sl = g_w1l + (size_t)m * M0v + k0 + ch * 8;
                const uint32_t da = sb + (m * G_SA + ch * 8) * 2;
                cpasync16(da, sa);
                cpasync16(da + G_ALO * 2, sl);
            }
            const uint32_t fb = smb + (G2_FP32 + s * G2_FPU16) * 2;
            #pragma unroll
            for (int r = 0; r < 4; r++) {
                const int idx = r * 256 + tid;
                const int k  = idx >> 5;
                const int j4 = (idx & 31) * 4;
                cpasync16(fb + idx * 16,
                          g_y0 + (size_t)(k0 + k) * NTOTv + j0 + j4);
            }
            cpcommit();
        };

        auto convert = [&](int i) {
            const int k0 = i * 32;
            const int s  = i & 1;
            const float* F = reinterpret_cast<const float*>(
                sm2 + G2_FP32 + s * G2_FPU16);
            uint16_t* S = sm2 + (size_t)s * G_STG;
            #pragma unroll
            for (int r = 0; r < 4; r++) {
                const int e  = r * 256 + tid;
                const int k  = e >> 5;
                const int j4 = (e & 31) * 4;
                float4 v = *(const float4*)(F + k * 128 + j4);
                const float sc = s_scale[k0 + k], sh = s_shift[k0 + k];
                v.x = fmaxf(fmaf(v.x, sc, sh), 0.0f);
                v.y = fmaxf(fmaf(v.y, sc, sh), 0.0f);
                v.z = fmaxf(fmaf(v.z, sc, sh), 0.0f);
                v.w = fmaxf(fmaf(v.w, sc, sh), 0.0f);
                uint32_t h0, l0, h1, l1;
                split2(v.x, v.y, h0, l0);
                split2(v.z, v.w, h1, l1);
                uint16_t* p = S + G_BHI + k * G_SB + j4;
                *(uint2*)(p)                   = make_uint2(h0, h1);
                *(uint2*)(p + (G_BLO - G_BHI)) = make_uint2(l0, l1);
            }
        };

        auto compute = [&](int i) {
            const uint32_t sb = smb + (i & 1) * G_STGB;
            #pragma unroll
            for (int ks = 0; ks < 2; ks++) {
                uint32_t ah[4][4], al[4][4], bh[2][4], bl[2][4];
                #pragma unroll
                for (int mi = 0; mi < 4; mi++) {
                    const uint32_t a = sb + aoff + mi * (16 * G_SA * 2) + ks * 32;
                    ldsm4(ah[mi], a);
                    ldsm4(al[mi], a + G_ALO * 2);
                }
                #pragma unroll
                for (int nb = 0; nb < 2; nb++) {
                    const uint32_t a = sb + boff + ks * (16 * G_SB * 2) + nb * 32;
                    ldsm4t(bh[nb], a);
                    ldsm4t(bl[nb], a + (G_BLO - G_BHI) * 2);
                }
                #pragma unroll
                for (int ni = 0; ni < 4; ni++) {
                    const uint32_t b0h = bh[ni >> 1][(ni & 1) * 2];
                    const uint32_t b1h = bh[ni >> 1][(ni & 1) * 2 + 1];
                    const uint32_t b0l = bl[ni >> 1][(ni & 1) * 2];
                    const uint32_t b1l = bl[ni >> 1][(ni & 1) * 2 + 1];
                    #pragma unroll
                    for (int mi = 0; mi < 4; mi++) {
                        mma16(acc[mi][ni], ah[mi], b0h, b1h);
                        mma16(acc[mi][ni], ah[mi], b0l, b1l);
                        mma16(acc[mi][ni], al[mi], b0h, b1h);
                    }
                }
            }
        };

        issue(0);

        #pragma unroll 1
        for (int i = 0; i < G2_NC; i++) {
            asm volatile("cp.async.wait_group 0;" ::: "memory");
            __syncthreads();
            convert(i);
            __syncthreads();
            if (i + 1 < G2_NC) issue(i + 1);
            compute(i);
        }

        #pragma unroll
        for (int mi = 0; mi < 4; mi++) {
            const int mrow = wm * 64 + mi * 16 + (lane >> 2);
            #pragma unroll
            for (int half = 0; half < 2; half++) {
                const int m = mrow + half * 8;
                const float bv = bias[m];
                float* orow = g_y1 + (size_t)m * NTOTv + j0 + wn * 32 + 2 * (lane & 3);
                float s = 0.0f, qq = 0.0f;
                #pragma unroll
                for (int ni = 0; ni < 4; ni++) {
                    const float v0 = acc[mi][ni][half * 2 + 0] + bv;
                    const float v1 = acc[mi][ni][half * 2 + 1] + bv;
                    s += v0 + v1;
                    qq = fmaf(v0, v0, qq);
                    qq = fmaf(v1, v1, qq);
                    *(float2*)(orow + ni * 8) = make_float2(v0, v1);
                }
                s  += __shfl_xor_sync(0xffffffffu, s, 1);
                s  += __shfl_xor_sync(0xffffffffu, s, 2);
                qq += __shfl_xor_sync(0xffffffffu, qq, 1);
                qq += __shfl_xor_sync(0xffffffffu, qq, 2);
                if ((lane & 3) == 0) {
                    atomicAdd(g_s1 + m, s);
                    atomicAdd(g_q1 + m, qq);
                }
            }
        }
    }
}

// ---------------------------------------------------------------------------
// Final BN2 + ReLU
// ---------------------------------------------------------------------------
__global__ __launch_bounds__(256) void bnrelu_out_kernel(float* __restrict__ out,
                                                         const float* __restrict__ g1v,
                                                         const float* __restrict__ be1v)
{
    __shared__ float ssc, ssh;
    const int ob = blockIdx.x * 1024;
    const int c  = (ob >> 12) & (M1v - 1);
    if (threadIdx.x == 0) {
        const float mean = g_s1[c] * (1.0f / NTOTv);
        const float var  = g_q1[c] * (1.0f / NTOTv) - mean * mean;
        const float sc = g1v[c] * rsqrtf(var + BN_EPS);
        ssc = sc;
        ssh = be1v[c] - mean * sc;
    }
    __syncthreads();

    const int o = ob + threadIdx.x * 4;
    const int n = o & (N1v - 1);
    const int b = o >> 19;
    float4 v = *(const float4*)(g_y1 + (size_t)c * NTOTv + b * N1v + n);
    v.x = fmaxf(fmaf(v.x, ssc, ssh), 0.0f);
    v.y = fmaxf(fmaf(v.y, ssc, ssh), 0.0f);
    v.z = fmaxf(fmaf(v.z, ssc, ssh), 0.0f);
    v.w = fmaxf(fmaf(v.w, ssc, ssh), 0.0f);
    *(float4*)(out + o) = v;
}

// ---------------------------------------------------------------------------
// Launch (R12 structure)
// ---------------------------------------------------------------------------
extern "C" void kernel_launch(void* const* d_in, const int* in_sizes, int n_in,
                              void* d_out, int out_size)
{
    const float* xyz1  = (const float*)d_in[0];
    const float* xyz2  = (const float*)d_in[1];
    const float* feat1 = (const float*)d_in[2];
    const float* feat2 = (const float*)d_in[3];
    const float* w0    = (const float*)d_in[4];
    const float* b0    = (const float*)d_in[5];
    const float* g0    = (const float*)d_in[6];
    const float* be0   = (const float*)d_in[7];
    const float* w1    = (const float*)d_in[8];
    const float* b1    = (const float*)d_in[9];
    const float* g1    = (const float*)d_in[10];
    const float* be1   = (const float*)d_in[11];
    float* out = (float*)d_out;

    static bool attr_done = false;
    if (!attr_done) {
        cudaFuncSetAttribute(interp_tiled,
            cudaFuncAttributeMaxDynamicSharedMemorySize, IT_SMEM);
        cudaFuncSetAttribute(gemm1,
            cudaFuncAttributeMaxDynamicSharedMemorySize, G1_SMEM);
        cudaFuncSetAttribute(gemm2,
            cudaFuncAttributeMaxDynamicSharedMemorySize, G2_SMEM);
        attr_done = true;
    }

    prep_knn<<<256 + (NB * C1v * N1v) / 1024, 256>>>(w0, w1, feat1, xyz1, xyz2);
    interp_tiled<<<NB * 8, 256, IT_SMEM>>>(feat2);
    gemm1<<<296, 256, G1_SMEM>>>(b0);
    gemm2<<<296, 256, G2_SMEM>>>(b1, g0, be0);
    bnrelu_out_kernel<<<(NTOTv * M1v) / 1024, 256>>>(out, g1, be1);
}

// round 16
// speedup vs baseline: 1.1307x; 1.1307x over previous
#include <cuda_runtime.h>
#include <cuda_bf16.h>
#include <cstdint>

// ---------------------------------------------------------------------------
// Problem constants
// ---------------------------------------------------------------------------
constexpr int NB   = 16;
constexpr int N1v  = 4096;
constexpr int N2v  = 1024;
constexpr int C1v  = 128;
constexpr int C2v  = 256;
constexpr int CINv = 384;
constexpr int M0v  = 256;
constexpr int M1v  = 128;
constexpr int NTOTv = NB * N1v;   // 65536
#define BN_EPS 1e-5f

// ---------------------------------------------------------------------------
// Scratch (device globals)
// ---------------------------------------------------------------------------
__device__ uint16_t g_Xh[(size_t)CINv * NTOTv];
__device__ uint16_t g_Xl[(size_t)CINv * NTOTv];
__device__ uint16_t g_w0h[M0v * CINv], g_w0l[M0v * CINv];
__device__ uint16_t g_w1h[M1v * M0v],  g_w1l[M1v * M0v];
__device__ float g_y0[(size_t)M0v * NTOTv];
__device__ float g_y1[(size_t)M1v * NTOTv];
__device__ int   g_idx3[NTOTv * 3];
__device__ float g_w3[NTOTv * 3];
__device__ float g_s0[M0v], g_q0[M0v];
__device__ float g_s1[M1v], g_q1[M1v];
__device__ int   g_ctr1, g_ctr2;

// ---------------------------------------------------------------------------
// Helpers
// ---------------------------------------------------------------------------
__device__ __forceinline__ uint32_t smem_u32(const void* p) {
    uint32_t a;
    asm("{ .reg .u64 t; cvta.to.shared.u64 t, %1; cvt.u32.u64 %0, t; }"
        : "=r"(a) : "l"(p));
    return a;
}

__device__ __forceinline__ void split2(float x0, float x1, uint32_t& h, uint32_t& l) {
    uint32_t hh;
    asm("cvt.rn.bf16x2.f32 %0, %1, %2;" : "=r"(hh) : "f"(x1), "f"(x0));
    const float h0 = __uint_as_float(hh << 16);
    const float h1 = __uint_as_float(hh & 0xFFFF0000u);
    const float l0 = x0 - h0;
    const float l1 = x1 - h1;
    uint32_t ll;
    asm("cvt.rn.bf16x2.f32 %0, %1, %2;" : "=r"(ll) : "f"(l1), "f"(l0));
    h = hh; l = ll;
}

__device__ __forceinline__ void split1(float x, uint16_t& h, uint16_t& l) {
    __nv_bfloat16 hb = __float2bfloat16(x);
    const float hf = __bfloat162float(hb);
    __nv_bfloat16 lb = __float2bfloat16(x - hf);
    h = *reinterpret_cast<uint16_t*>(&hb);
    l = *reinterpret_cast<uint16_t*>(&lb);
}

__device__ __forceinline__ void mma16(float* d, const uint32_t* a,
                                      uint32_t b0, uint32_t b1) {
    asm volatile(
        "mma.sync.aligned.m16n8k16.row.col.f32.bf16.bf16.f32 "
        "{%0,%1,%2,%3}, {%4,%5,%6,%7}, {%8,%9}, {%0,%1,%2,%3};"
        : "+f"(d[0]), "+f"(d[1]), "+f"(d[2]), "+f"(d[3])
        : "r"(a[0]), "r"(a[1]), "r"(a[2]), "r"(a[3]), "r"(b0), "r"(b1));
}

__device__ __forceinline__ void ldsm4(uint32_t* r, uint32_t a) {
    asm volatile("ldmatrix.sync.aligned.m8n8.x4.shared.b16 {%0,%1,%2,%3}, [%4];"
        : "=r"(r[0]), "=r"(r[1]), "=r"(r[2]), "=r"(r[3]) : "r"(a));
}
__device__ __forceinline__ void ldsm4t(uint32_t* r, uint32_t a) {
    asm volatile("ldmatrix.sync.aligned.m8n8.x4.trans.shared.b16 {%0,%1,%2,%3}, [%4];"
        : "=r"(r[0]), "=r"(r[1]), "=r"(r[2]), "=r"(r[3]) : "r"(a));
}
__device__ __forceinline__ void cpasync16(uint32_t dst, const void* src) {
    asm volatile("cp.async.cg.shared.global [%0], [%1], 16;" :: "r"(dst), "l"(src));
}
__device__ __forceinline__ void cpcommit() {
    asm volatile("cp.async.commit_group;" ::: "memory");
}

// ---------------------------------------------------------------------------
// Shared GEMM SMEM geometry: A[128][40] u16, B [k][j] 32x[136]
// ---------------------------------------------------------------------------
constexpr int G_SA    = 40;
constexpr int G_SB    = 136;
constexpr int G_ALO   = 128 * G_SA;
constexpr int G_BHI   = 2 * 128 * G_SA;
constexpr int G_BLO   = G_BHI + 32 * G_SB;
constexpr int G_STG   = G_BHI + 2 * 32 * G_SB;   // 18944 u16
constexpr int G_STGB  = G_STG * 2;               // 37888 bytes

// ---------------------------------------------------------------------------
// prep_knn: blocks [0,512) = 3-NN pair-split (2 lanes/query, 512 cands each,
// branchy update + shfl merge); blocks [512, 8704) = prep.
// ---------------------------------------------------------------------------
__global__ __launch_bounds__(256) void prep_knn(const float* __restrict__ w0,
                                                const float* __restrict__ w1,
                                                const float* __restrict__ feat1,
                                                const float* __restrict__ xyz1,
                                                const float* __restrict__ xyz2)
{
    __shared__ float4 s2[N2v];
    const int tid = threadIdx.x;

    if (blockIdx.x < 512) {
        const int b  = blockIdx.x >> 5;        // 32 blocks per batch
        const int nb = blockIdx.x & 31;        // 128 queries per block
        const float* x2 = xyz2 + (size_t)b * N2v * 3;
        for (int i = tid; i < N2v; i += 256)
            s2[i] = make_float4(x2[i * 3 + 0], x2[i * 3 + 1], x2[i * 3 + 2], 0.0f);
        __syncthreads();

        const int n = nb * 128 + (tid >> 1);
        const int h = tid & 1;
        const float* p = xyz1 + ((size_t)b * N1v + n) * 3;
        const float px = p[0], py = p[1], pz = p[2];

        float d0 = 1e30f, d1 = 1e30f, d2 = 1e30f;
        int   i0 = 0,     i1 = 0,     i2 = 0;

        const int beg = h * 512;
        #pragma unroll 4
        for (int ii = 0; ii < 512; ii++) {
            const int i = beg + ii;
            const float4 qv = s2[i];
            const float dx = px - qv.x, dy = py - qv.y, dz = pz - qv.z;
            float d = dx * dx;
            d = fmaf(dy, dy, d);
            d = fmaf(dz, dz, d);
            if (d < d2) {
                if (d < d1) {
                    d2 = d1; i2 = i1;
                    if (d < d0) { d1 = d0; i1 = i0; d0 = d; i0 = i; }
                    else        { d1 = d;  i1 = i; }
                } else { d2 = d; i2 = i; }
            }
        }

        // merge with partner lane's top-3 (3 insertions, branchy)
        const unsigned fm = 0xffffffffu;
        const float e0 = __shfl_xor_sync(fm, d0, 1);
        const float e1 = __shfl_xor_sync(fm, d1, 1);
        const float e2 = __shfl_xor_sync(fm, d2, 1);
        const int   j0 = __shfl_xor_sync(fm, i0, 1);
        const int   j1 = __shfl_xor_sync(fm, i1, 1);
        const int   j2 = __shfl_xor_sync(fm, i2, 1);
        #pragma unroll
        for (int s = 0; s < 3; s++) {
            const float e = (s == 0) ? e0 : (s == 1) ? e1 : e2;
            const int   j = (s == 0) ? j0 : (s == 1) ? j1 : j2;
            if (e < d2) {
                if (e < d1) {
                    d2 = d1; i2 = i1;
                    if (e < d0) { d1 = d0; i1 = i0; d0 = e; i0 = j; }
                    else        { d1 = e;  i1 = j; }
                } else { d2 = e; i2 = j; }
            }
        }

        if (h == 0) {
            const float w0_ = 1.0f / (d0 + 1e-8f);
            const float w1_ = 1.0f / (d1 + 1e-8f);
            const float w2_ = 1.0f / (d2 + 1e-8f);
            const float inv = 1.0f / (w0_ + w1_ + w2_);
            const int base = ((size_t)b * N1v + n) * 3;
            g_idx3[base + 0] = i0; g_idx3[base + 1] = i1; g_idx3[base + 2] = i2;
            g_w3[base + 0] = w0_ * inv;
            g_w3[base + 1] = w1_ * inv;
            g_w3[base + 2] = w2_ * inv;
        }
    } else {
        const int pidx = blockIdx.x - 512;
        const int gidx = pidx * 256 + tid;

        if (pidx == 0) {
            if (tid < M0v) { g_s0[tid] = 0.0f; g_q0[tid] = 0.0f; }
            if (tid < M1v) { g_s1[tid] = 0.0f; g_q1[tid] = 0.0f; }
            if (tid == 0)  { g_ctr1 = 0; g_ctr2 = 0; }
        }
        if (gidx < M0v * CINv) {
            uint16_t h, l;
            split1(w0[gidx], h, l);
            g_w0h[gidx] = h;
            g_w0l[gidx] = l;
        }
        if (gidx < M1v * M0v) {
            uint16_t h, l;
            split1(w1[gidx], h, l);
            g_w1h[gidx] = h;
            g_w1l[gidx] = l;
        }

        const int e = gidx * 4;
        float4 v = *(const float4*)(feat1 + e);
        const int b = e >> 19, c = (e >> 12) & 127, n = e & 4095;
        const size_t dst = (size_t)c * NTOTv + b * N1v + n;
        uint32_t h0, l0, h1, l1;
        split2(v.x, v.y, h0, l0);
        split2(v.z, v.w, h1, l1);
        *(uint32_t*)(g_Xh + dst)     = h0;
        *(uint32_t*)(g_Xh + dst + 2) = h1;
        *(uint32_t*)(g_Xl + dst)     = l0;
        *(uint32_t*)(g_Xl + dst + 2) = l1;
    }
}

// ---------------------------------------------------------------------------
// Interpolation (single launch, 128 blocks)
// ---------------------------------------------------------------------------
constexpr int IT_STR  = 36;
constexpr int IT_SMEM = N2v * IT_STR * 4;

__global__ __launch_bounds__(256) void interp_tiled(const float* __restrict__ feat2)
{
    extern __shared__ float tile[];
    const int b  = blockIdx.x >> 3;
    const int cg = blockIdx.x & 7;
    const float* src = feat2 + ((size_t)b * C2v + cg * 32) * N2v;
    for (int x = threadIdx.x; x < 32 * N2v; x += 256) {
        const int c = x >> 10, i = x & 1023;
        tile[i * IT_STR + c] = src[x];
    }
    __syncthreads();

    for (int jb = threadIdx.x * 2; jb < N1v; jb += 512) {
        const int jg = b * N1v + jb;
        const int pa = jg * 3;
        const int ia0 = g_idx3[pa + 0], ia1 = g_idx3[pa + 1], ia2 = g_idx3[pa + 2];
        const int ib0 = g_idx3[pa + 3], ib1 = g_idx3[pa + 4], ib2 = g_idx3[pa + 5];
        const float wa0 = g_w3[pa + 0], wa1 = g_w3[pa + 1], wa2 = g_w3[pa + 2];
        const float wb0 = g_w3[pa + 3], wb1 = g_w3[pa + 4], wb2 = g_w3[pa + 5];
        const float* ta0 = tile + ia0 * IT_STR;
        const float* ta1 = tile + ia1 * IT_STR;
        const float* ta2 = tile + ia2 * IT_STR;
        const float* tb0 = tile + ib0 * IT_STR;
        const float* tb1 = tile + ib1 * IT_STR;
        const float* tb2 = tile + ib2 * IT_STR;

        #pragma unroll
        for (int c4 = 0; c4 < 8; c4++) {
            const float4 A0 = *(const float4*)(ta0 + c4 * 4);
            const float4 A1 = *(const float4*)(ta1 + c4 * 4);
            const float4 A2 = *(const float4*)(ta2 + c4 * 4);
            const float4 B0 = *(const float4*)(tb0 + c4 * 4);
            const float4 B1 = *(const float4*)(tb1 + c4 * 4);
            const float4 B2 = *(const float4*)(tb2 + c4 * 4);
            float va[4], vb[4];
            va[0] = fmaf(wa2, A2.x, fmaf(wa1, A1.x, wa0 * A0.x));
            va[1] = fmaf(wa2, A2.y, fmaf(wa1, A1.y, wa0 * A0.y));
            va[2] = fmaf(wa2, A2.z, fmaf(wa1, A1.z, wa0 * A0.z));
            va[3] = fmaf(wa2, A2.w, fmaf(wa1, A1.w, wa0 * A0.w));
            vb[0] = fmaf(wb2, B2.x, fmaf(wb1, B1.x, wb0 * B0.x));
            vb[1] = fmaf(wb2, B2.y, fmaf(wb1, B1.y, wb0 * B0.y));
            vb[2] = fmaf(wb2, B2.z, fmaf(wb1, B1.z, wb0 * B0.z));
            vb[3] = fmaf(wb2, B2.w, fmaf(wb1, B1.w, wb0 * B0.w));
            #pragma unroll
            for (int qx = 0; qx < 4; qx++) {
                uint32_t h, l;
                split2(va[qx], vb[qx], h, l);
                const size_t d = (size_t)(C1v + cg * 32 + c4 * 4 + qx) * NTOTv + jg;
                *(uint32_t*)(g_Xh + d) = h;
                *(uint32_t*)(g_Xl + d) = l;
            }
        }
    }
}

// ---------------------------------------------------------------------------
// GEMM1 (R12: persistent + cross-tile pipelining)
// ---------------------------------------------------------------------------
constexpr int G1_NC   = CINv / 32;               // 12
constexpr int G1_SMEM = 3 * G_STGB;              // 113664 bytes
constexpr int G1_NT   = (M0v / 128) * (NTOTv / 128);  // 1024

__global__ __launch_bounds__(256, 2) void gemm1(const float* __restrict__ bias)
{
    extern __shared__ uint16_t sm1[];
    __shared__ int sh_t[2];
    const uint32_t smb = smem_u32(sm1);
    const int tid  = threadIdx.x;
    const int lane = tid & 31;
    const int wid  = tid >> 5;
    const int wm   = wid >> 2;
    const int wn   = wid & 3;

    const int q  = lane >> 3;
    const int jj = lane & 7;
    const uint32_t aoff = ((wm * 64 + (q & 1) * 8 + jj) * G_SA + (q >> 1) * 8) * 2;
    const uint32_t boff = (G_BHI + ((q & 1) * 8 + jj) * G_SB
                           + wn * 32 + (q >> 1) * 8) * 2;

    auto issue = [&](int m0g, int j0, int c) {
        const int k0 = c * 32;
        const uint32_t sb = smb + (c % 3) * G_STGB;
        #pragma unroll
        for (int g = 0; g < 2; g++) {
            const int idx = 2 * tid + g;
            const int m  = idx >> 2, ch = idx & 3;
            const uint16_t* sa = g_w0h + (size_t)(m0g + m) * CINv + k0 + ch * 8;
            const uint16_t* sl = g_w0l + (size_t)(m0g + m) * CINv + k0 + ch * 8;
            const uint32_t da = sb + (m * G_SA + ch * 8) * 2;
            cpasync16(da, sa);
            cpasync16(da + G_ALO * 2, sl);
            const int k = idx >> 4, ch2 = idx & 15;
            const uint16_t* sbh = g_Xh + (size_t)(k0 + k) * NTOTv + j0 + ch2 * 8;
            const uint16_t* sbl = g_Xl + (size_t)(k0 + k) * NTOTv + j0 + ch2 * 8;
            const uint32_t db = sb + (G_BHI + k * G_SB + ch2 * 8) * 2;
            cpasync16(db, sbh);
            cpasync16(db + (G_BLO - G_BHI) * 2, sbl);
        }
        cpcommit();
    };

    if (tid == 0) sh_t[0] = atomicAdd(&g_ctr1, 1);
    __syncthreads();
    int t = sh_t[0];
    if (t >= G1_NT) return;
    int pr = 0;
    int m0g = (t & 1) * 128;
    int j0  = (t >> 1) * 128;
    issue(m0g, j0, 0);
    issue(m0g, j0, 1);

    int tn = 0;
    for (;;) {
        float acc[4][4][4] = {};

        auto compute = [&](int i) {
            const uint32_t sb = smb + (i % 3) * G_STGB;
            #pragma unroll
            for (int ks = 0; ks < 2; ks++) {
                uint32_t ah[4][4], al[4][4], bh[2][4], bl[2][4];
                #pragma unroll
                for (int mi = 0; mi < 4; mi++) {
                    const uint32_t a = sb + aoff + mi * (16 * G_SA * 2) + ks * 32;
                    ldsm4(ah[mi], a);
                    ldsm4(al[mi], a + G_ALO * 2);
                }
                #pragma unroll
                for (int nb = 0; nb < 2; nb++) {
                    const uint32_t a = sb + boff + ks * (16 * G_SB * 2) + nb * 32;
                    ldsm4t(bh[nb], a);
                    ldsm4t(bl[nb], a + (G_BLO - G_BHI) * 2);
                }
                #pragma unroll
                for (int ni = 0; ni < 4; ni++) {
                    const uint32_t b0h = bh[ni >> 1][(ni & 1) * 2];
                    const uint32_t b1h = bh[ni >> 1][(ni & 1) * 2 + 1];
                    const uint32_t b0l = bl[ni >> 1][(ni & 1) * 2];
                    const uint32_t b1l = bl[ni >> 1][(ni & 1) * 2 + 1];
                    #pragma unroll
                    for (int mi = 0; mi < 4; mi++) {
                        mma16(acc[mi][ni], ah[mi], b0h, b1h);
                        mma16(acc[mi][ni], ah[mi], b0l, b1l);
                        mma16(acc[mi][ni], al[mi], b0h, b1h);
                    }
                }
            }
        };

        #pragma unroll 1
        for (int i = 0; i < G1_NC; i++) {
            if (i == G1_NC - 3 && tid == 0)
                sh_t[pr ^ 1] = atomicAdd(&g_ctr1, 1);
            if (i == G1_NC - 1 && tn >= G1_NT)
                asm volatile("cp.async.wait_group 0;" ::: "memory");
            else
                asm volatile("cp.async.wait_group 1;" ::: "memory");
            __syncthreads();
            if (i == G1_NC - 2) tn = sh_t[pr ^ 1];
            if (i < G1_NC - 2) {
                issue(m0g, j0, i + 2);
            } else if (tn < G1_NT) {
                issue((tn & 1) * 128, (tn >> 1) * 128, i - (G1_NC - 2));
            }
            compute(i);
        }

        #pragma unroll
        for (int mi = 0; mi < 4; mi++) {
            const int mrow = m0g + wm * 64 + mi * 16 + (lane >> 2);
            #pragma unroll
            for (int half = 0; half < 2; half++) {
                const int m = mrow + half * 8;
                const float bv = bias[m];
                float* orow = g_y0 + (size_t)m * NTOTv + j0 + wn * 32 + 2 * (lane & 3);
                float s = 0.0f, qq = 0.0f;
                #pragma unroll
                for (int ni = 0; ni < 4; ni++) {
                    const float v0 = acc[mi][ni][half * 2 + 0] + bv;
                    const float v1 = acc[mi][ni][half * 2 + 1] + bv;
                    s += v0 + v1;
                    qq = fmaf(v0, v0, qq);
                    qq = fmaf(v1, v1, qq);
                    *(float2*)(orow + ni * 8) = make_float2(v0, v1);
                }
                s  += __shfl_xor_sync(0xffffffffu, s, 1);
                s  += __shfl_xor_sync(0xffffffffu, s, 2);
                qq += __shfl_xor_sync(0xffffffffu, qq, 1);
                qq += __shfl_xor_sync(0xffffffffu, qq, 2);
                if ((lane & 3) == 0) {
                    atomicAdd(g_s0 + m, s);
                    atomicAdd(g_q0 + m, qq);
                }
            }
        }

        if (tn >= G1_NT) break;
        t = tn;
        m0g = (t & 1) * 128;
        j0  = (t >> 1) * 128;
        pr ^= 1;
    }
}

// ---------------------------------------------------------------------------
// GEMM2 (R12: persistent + cross-tile pipelining, depth-1, fp32 staging)
// ---------------------------------------------------------------------------
constexpr int G2_NC    = M0v / 32;             // 8
constexpr int G2_FP32  = 2 * G_STG;
constexpr int G2_FPU16 = 32 * 128 * 2;
constexpr int G2_SMEM  = 2 * G_STGB + 2 * 16384;  // 108544 bytes
constexpr int G2_NT    = NTOTv / 128;          // 512

__global__ __launch_bounds__(256, 2) void gemm2(const float* __restrict__ bias,
                                                const float* __restrict__ g0v,
                                                const float* __restrict__ be0v)
{
    extern __shared__ uint16_t sm2[];
    __shared__ float s_scale[M0v], s_shift[M0v];
    __shared__ int sh_t[2];
    const uint32_t smb = smem_u32(sm2);

    const int tid  = threadIdx.x;
    const int lane = tid & 31;
    const int wid  = tid >> 5;
    const int wm   = wid >> 2;
    const int wn   = wid & 3;

    {
        const int c = tid;
        const float mean = g_s0[c] * (1.0f / NTOTv);
        const float var  = g_q0[c] * (1.0f / NTOTv) - mean * mean;
        const float sc = g0v[c] * rsqrtf(var + BN_EPS);
        s_scale[c] = sc;
        s_shift[c] = be0v[c] - mean * sc;
    }

    const int q  = lane >> 3;
    const int jj = lane & 7;
    const uint32_t aoff = ((wm * 64 + (q & 1) * 8 + jj) * G_SA + (q >> 1) * 8) * 2;
    const uint32_t boff = (G_BHI + ((q & 1) * 8 + jj) * G_SB
                           + wn * 32 + (q >> 1) * 8) * 2;

    auto issue = [&](int j0, int c) {
        const int k0 = c * 32;
        const int s  = c & 1;
        const uint32_t sb = smb + s * G_STGB;
        #pragma unroll
        for (int g = 0; g < 2; g++) {
            const int idx = 2 * tid + g;
            const int m  = idx >> 2, ch = idx & 3;
            const uint16_t* sa = g_w1h + (size_t)m * M0v + k0 + ch * 8;
            const uint16_t* sl = g_w1l + (size_t)m * M0v + k0 + ch * 8;
            const uint32_t da = sb + (m * G_SA + ch * 8) * 2;
            cpasync16(da, sa);
            cpasync16(da + G_ALO * 2, sl);
        }
        const uint32_t fb = smb + (G2_FP32 + s * G2_FPU16) * 2;
        #pragma unroll
        for (int r = 0; r < 4; r++) {
            const int idx = r * 256 + tid;
            const int k  = idx >> 5;
            const int j4 = (idx & 31) * 4;
            cpasync16(fb + idx * 16,
                      g_y0 + (size_t)(k0 + k) * NTOTv + j0 + j4);
        }
        cpcommit();
    };

    auto convert = [&](int i) {
        const int k0 = i * 32;
        const int s  = i & 1;
        const float* F = reinterpret_cast<const float*>(
            sm2 + G2_FP32 + s * G2_FPU16);
        uint16_t* S = sm2 + (size_t)s * G_STG;
        #pragma unroll
        for (int r = 0; r < 4; r++) {
            const int e  = r * 256 + tid;
            const int k  = e >> 5;
            const int j4 = (e & 31) * 4;
            float4 v = *(const float4*)(F + k * 128 + j4);
            const float sc = s_scale[k0 + k], sh = s_shift[k0 + k];
            v.x = fmaxf(fmaf(v.x, sc, sh), 0.0f);
            v.y = fmaxf(fmaf(v.y, sc, sh), 0.0f);
            v.z = fmaxf(fmaf(v.z, sc, sh), 0.0f);
            v.w = fmaxf(fmaf(v.w, sc, sh), 0.0f);
            uint32_t h0, l0, h1, l1;
            split2(v.x, v.y, h0, l0);
            split2(v.z, v.w, h1, l1);
            uint16_t* p = S + G_BHI + k * G_SB + j4;
            *(uint2*)(p)                   = make_uint2(h0, h1);
            *(uint2*)(p + (G_BLO - G_BHI)) = make_uint2(l0, l1);
        }
    };

    if (tid == 0) sh_t[0] = atomicAdd(&g_ctr2, 1);
    __syncthreads();
    int t = sh_t[0];
    if (t >= G2_NT) return;
    int pr = 0;
    int j0 = t * 128;
    issue(j0, 0);

    int tn = 0;
    for (;;) {
        float acc[4][4][4] = {};

        auto compute = [&](int i) {
            const uint32_t sb = smb + (i & 1) * G_STGB;
            #pragma unroll
            for (int ks = 0; ks < 2; ks++) {
                uint32_t ah[4][4], al[4][4], bh[2][4], bl[2][4];
                #pragma unroll
                for (int mi = 0; mi < 4; mi++) {
                    const uint32_t a = sb + aoff + mi * (16 * G_SA * 2) + ks * 32;
                    ldsm4(ah[mi], a);
                    ldsm4(al[mi], a + G_ALO * 2);
                }
                #pragma unroll
                for (int nb = 0; nb < 2; nb++) {
                    const uint32_t a = sb + boff + ks * (16 * G_SB * 2) + nb * 32;
                    ldsm4t(bh[nb], a);
                    ldsm4t(bl[nb], a + (G_BLO - G_BHI) * 2);
                }
                #pragma unroll
                for (int ni = 0; ni < 4; ni++) {
                    const uint32_t b0h = bh[ni >> 1][(ni & 1) * 2];
                    const uint32_t b1h = bh[ni >> 1][(ni & 1) * 2 + 1];
                    const uint32_t b0l = bl[ni >> 1][(ni & 1) * 2];
                    const uint32_t b1l = bl[ni >> 1][(ni & 1) * 2 + 1];
                    #pragma unroll
                    for (int mi = 0; mi < 4; mi++) {
                        mma16(acc[mi][ni], ah[mi], b0h, b1h);
                        mma16(acc[mi][ni], ah[mi], b0l, b1l);
                        mma16(acc[mi][ni], al[mi], b0h, b1h);
                    }
                }
            }
        };

        #pragma unroll 1
        for (int i = 0; i < G2_NC; i++) {
            if (i == G2_NC - 2 && tid == 0)
                sh_t[pr ^ 1] = atomicAdd(&g_ctr2, 1);
            asm volatile("cp.async.wait_group 0;" ::: "memory");
            __syncthreads();
            if (i == G2_NC - 1) tn = sh_t[pr ^ 1];
            convert(i);
            __syncthreads();
            if (i < G2_NC - 1)         issue(j0, i + 1);
            else if (tn < G2_NT)       issue(tn * 128, 0);
            compute(i);
        }

        #pragma unroll
        for (int mi = 0; mi < 4; mi++) {
            const int mrow = wm * 64 + mi * 16 + (lane >> 2);
            #pragma unroll
            for (int half = 0; half < 2; half++) {
                const int m = mrow + half * 8;
                const float bv = bias[m];
                float* orow = g_y1 + (size_t)m * NTOTv + j0 + wn * 32 + 2 * (lane & 3);
                float s = 0.0f, qq = 0.0f;
                #pragma unroll
                for (int ni = 0; ni < 4; ni++) {
                    const float v0 = acc[mi][ni][half * 2 + 0] + bv;
                    const float v1 = acc[mi][ni][half * 2 + 1] + bv;
                    s += v0 + v1;
                    qq = fmaf(v0, v0, qq);
                    qq = fmaf(v1, v1, qq);
                    *(float2*)(orow + ni * 8) = make_float2(v0, v1);
                }
                s  += __shfl_xor_sync(0xffffffffu, s, 1);
                s  += __shfl_xor_sync(0xffffffffu, s, 2);
                qq += __shfl_xor_sync(0xffffffffu, qq, 1);
                qq += __shfl_xor_sync(0xffffffffu, qq, 2);
                if ((lane & 3) == 0) {
                    atomicAdd(g_s1 + m, s);
                    atomicAdd(g_q1 + m, qq);
                }
            }
        }

        if (tn >= G2_NT) break;
        j0 = tn * 128;
        pr ^= 1;
    }
}

// ---------------------------------------------------------------------------
// Final BN2 + ReLU
// ---------------------------------------------------------------------------
__global__ __launch_bounds__(256) void bnrelu_out_kernel(float* __restrict__ out,
                                                         const float* __restrict__ g1v,
                                                         const float* __restrict__ be1v)
{
    __shared__ float ssc, ssh;
    const int ob = blockIdx.x * 1024;
    const int c  = (ob >> 12) & (M1v - 1);
    if (threadIdx.x == 0) {
        const float mean = g_s1[c] * (1.0f / NTOTv);
        const float var  = g_q1[c] * (1.0f / NTOTv) - mean * mean;
        const float sc = g1v[c] * rsqrtf(var + BN_EPS);
        ssc = sc;
        ssh = be1v[c] - mean * sc;
    }
    __syncthreads();

    const int o = ob + threadIdx.x * 4;
    const int n = o & (N1v - 1);
    const int b = o >> 19;
    float4 v = *(const float4*)(g_y1 + (size_t)c * NTOTv + b * N1v + n);
    v.x = fmaxf(fmaf(v.x, ssc, ssh), 0.0f);
    v.y = fmaxf(fmaf(v.y, ssc, ssh), 0.0f);
    v.z = fmaxf(fmaf(v.z, ssc, ssh), 0.0f);
    v.w = fmaxf(fmaf(v.w, ssc, ssh), 0.0f);
    *(float4*)(out + o) = v;
}

// ---------------------------------------------------------------------------
// Launch (R12 structure)
// ---------------------------------------------------------------------------
extern "C" void kernel_launch(void* const* d_in, const int* in_sizes, int n_in,
                              void* d_out, int out_size)
{
    const float* xyz1  = (const float*)d_in[0];
    const float* xyz2  = (const float*)d_in[1];
    const float* feat1 = (const float*)d_in[2];
    const float* feat2 = (const float*)d_in[3];
    const float* w0    = (const float*)d_in[4];
    const float* b0    = (const float*)d_in[5];
    const float* g0    = (const float*)d_in[6];
    const float* be0   = (const float*)d_in[7];
    const float* w1    = (const float*)d_in[8];
    const float* b1    = (const float*)d_in[9];
    const float* g1    = (const float*)d_in[10];
    const float* be1   = (const float*)d_in[11];
    float* out = (float*)d_out;

    static bool attr_done = false;
    if (!attr_done) {
        cudaFuncSetAttribute(interp_tiled,
            cudaFuncAttributeMaxDynamicSharedMemorySize, IT_SMEM);
        cudaFuncSetAttribute(gemm1,
            cudaFuncAttributeMaxDynamicSharedMemorySize, G1_SMEM);
        cudaFuncSetAttribute(gemm2,
            cudaFuncAttributeMaxDynamicSharedMemorySize, G2_SMEM);
        attr_done = true;
    }

    prep_knn<<<512 + (NB * C1v * N1v) / 1024, 256>>>(w0, w1, feat1, xyz1, xyz2);
    interp_tiled<<<NB * 8, 256, IT_SMEM>>>(feat2);
    gemm1<<<296, 256, G1_SMEM>>>(b0);
    gemm2<<<296, 256, G2_SMEM>>>(b1, g0, be0);
    bnrelu_out_kernel<<<(NTOTv * M1v) / 1024, 256>>>(out, g1, be1);
}